// round 14
// baseline (speedup 1.0000x reference)
#include <cuda_runtime.h>
#include <cstdint>
#include <math.h>

#define T_ 1024
#define H_ 2048
#define E_ 64
#define KTOP 8
#define I_ 1024
#define NSLOT (T_*KTOP)

// ---------------- scratch (device globals) ----------------
__device__ float g_xs[T_*H_];           // x rounded-to-nearest at tf32 grid
__device__ float g_logits[T_*E_];
__device__ int   g_cnt[E_];
__device__ int   g_off[E_];
__device__ int   g_cur[E_];
__device__ int   g_tok[NSLOT + 256];
__device__ float g_wt[NSLOT + 256];
__device__ int   g_tk_idx[NSLOT];
__device__ float g_tk_wt[NSLOT];
__device__ float g_act[(size_t)(NSLOT + 256) * I_];   // pre-rounded for down GEMM

#define SWZ(o) ((uint32_t)(o) ^ ((((uint32_t)(o)) >> 3) & 0x70))
// round-to-nearest at the 13-bit truncation the tf32 MMA applies: +half-ulp
#define RND13(b) ((b) + 0x1000u)

__device__ __forceinline__ uint32_t smem_u32(const void* p) {
    uint32_t a;
    asm("{ .reg .u64 t; cvta.to.shared.u64 t, %1; cvt.u32.u64 %0, t; }" : "=r"(a) : "l"(p));
    return a;
}
__device__ __forceinline__ float rndf(float x) {
    return __uint_as_float(RND13(__float_as_uint(x)));
}

#define CPA16(dst, src) \
    asm volatile("cp.async.cg.shared.global [%0], [%1], 16;" :: "r"(dst), "l"(src))
#define CPCOMMIT() asm volatile("cp.async.commit_group;" ::: "memory")
#define CPWAIT(n)  asm volatile("cp.async.wait_group %0;" :: "n"(n) : "memory")

#define LDSM4(r0,r1,r2,r3,a) \
    asm volatile("ldmatrix.sync.aligned.m8n8.x4.shared.b16 {%0,%1,%2,%3}, [%4];" \
        : "=r"(r0), "=r"(r1), "=r"(r2), "=r"(r3) : "r"(a))

__device__ __forceinline__ void mma8(float* c, const uint32_t* a, uint32_t b0, uint32_t b1) {
    asm volatile(
        "mma.sync.aligned.m16n8k8.row.col.f32.tf32.tf32.f32 "
        "{%0,%1,%2,%3}, {%4,%5,%6,%7}, {%8,%9}, {%0,%1,%2,%3};\n"
        : "+f"(c[0]), "+f"(c[1]), "+f"(c[2]), "+f"(c[3])
        : "r"(a[0]), "r"(a[1]), "r"(a[2]), "r"(a[3]), "r"(b0), "r"(b1));
}

// ---------------- 0: zero output + counters + pre-round x ----------------
__global__ void k_zero(float* __restrict__ out, const float* __restrict__ x) {
    int i = blockIdx.x * blockDim.x + threadIdx.x;
    if (i < T_*H_) { out[i] = 0.f; g_xs[i] = rndf(x[i]); }
    if (i < E_) { g_cnt[i] = 0; g_cur[i] = 0; }
}

// ---------------- 1: router logits (fp32 exact) ----------------
__global__ void __launch_bounds__(256) k_router(const float* __restrict__ x,
                                                const float* __restrict__ gw) {
    __shared__ float xs[4 * H_];
    int t0 = blockIdx.x * 4;
    for (int i = threadIdx.x; i < 4 * H_; i += 256)
        xs[i] = x[(size_t)t0 * H_ + i];
    __syncthreads();
    int warp = threadIdx.x >> 5, lane = threadIdx.x & 31;
    for (int ei = 0; ei < 8; ei++) {
        int e = warp * 8 + ei;
        const float* w = gw + (size_t)e * H_;
        float a0 = 0.f, a1 = 0.f, a2 = 0.f, a3 = 0.f;
        for (int h = lane; h < H_; h += 32) {
            float wv = w[h];
            a0 = fmaf(wv, xs[h],        a0);
            a1 = fmaf(wv, xs[H_   + h], a1);
            a2 = fmaf(wv, xs[2*H_ + h], a2);
            a3 = fmaf(wv, xs[3*H_ + h], a3);
        }
        #pragma unroll
        for (int o = 16; o; o >>= 1) {
            a0 += __shfl_xor_sync(0xffffffffu, a0, o);
            a1 += __shfl_xor_sync(0xffffffffu, a1, o);
            a2 += __shfl_xor_sync(0xffffffffu, a2, o);
            a3 += __shfl_xor_sync(0xffffffffu, a3, o);
        }
        if (lane == 0) {
            g_logits[(t0+0)*E_ + e] = a0;
            g_logits[(t0+1)*E_ + e] = a1;
            g_logits[(t0+2)*E_ + e] = a2;
            g_logits[(t0+3)*E_ + e] = a3;
        }
    }
}

// ---------------- 2: softmax + top-8, warp per token (no local-mem spills) ----------------
__global__ void __launch_bounds__(256) k_topk() {
    int wid = threadIdx.x >> 5, lane = threadIdx.x & 31;
    int t = blockIdx.x * 8 + wid;
    if (t >= T_) return;
    const float* lg = g_logits + t * E_;
    float l0 = lg[lane], l1 = lg[lane + 32];
    float mx = fmaxf(l0, l1);
    #pragma unroll
    for (int o = 16; o; o >>= 1) mx = fmaxf(mx, __shfl_xor_sync(0xffffffffu, mx, o));
    float e0 = expf(l0 - mx), e1 = expf(l1 - mx);
    float s = e0 + e1;
    #pragma unroll
    for (int o = 16; o; o >>= 1) s += __shfl_xor_sync(0xffffffffu, s, o);
    float inv = 1.f / s;
    #pragma unroll
    for (int k = 0; k < KTOP; k++) {
        float v; int idx;
        if (e0 >= e1) { v = e0; idx = lane; } else { v = e1; idx = lane + 32; }
        #pragma unroll
        for (int o = 16; o; o >>= 1) {
            float ov = __shfl_xor_sync(0xffffffffu, v, o);
            int   oi = __shfl_xor_sync(0xffffffffu, idx, o);
            if (ov > v || (ov == v && oi < idx)) { v = ov; idx = oi; }
        }
        if (lane == 0) {
            g_tk_idx[t*KTOP + k] = idx;
            g_tk_wt [t*KTOP + k] = v * inv;
            atomicAdd(&g_cnt[idx], 1);
        }
        if (idx == lane) e0 = -1.f;
        else if (idx == lane + 32) e1 = -1.f;
    }
}

// ---------------- 3: scan ----------------
__global__ void k_scan() {
    if (threadIdx.x == 0) {
        int acc = 0;
        for (int e = 0; e < E_; e++) { g_off[e] = acc; acc += g_cnt[e]; }
    }
}

// ---------------- 4: slot fill ----------------
__global__ void k_fill() {
    int i = blockIdx.x * blockDim.x + threadIdx.x;
    if (i >= NSLOT) return;
    int t = i >> 3;
    int e = g_tk_idx[i];
    int pos = atomicAdd(&g_cur[e], 1);
    int slot = g_off[e] + pos;
    g_tok[slot] = t;
    g_wt [slot] = g_tk_wt[i];
}

// ---------------- 5: grouped gate/up GEMM, cp.async + tf32 mma, warp tile 64x(16G+16U) ----------------
// Block M=128, N=64 i-cols (G and U). 8 warps: wm=wid&1 (M 64), wn=wid>>2? -> wn=wid>>1 (cols 16).
// Stage: A 16KB | G 8KB | U 8KB = 32KB x3 = 96KB, 2 blocks/SM.
__global__ void __launch_bounds__(256, 2) k_gateup(const float* __restrict__ wg,
                                                   const float* __restrict__ wu) {
    extern __shared__ char smem[];
    const int e   = blockIdx.z;
    const int cnt = g_cnt[e];
    const int mtb = blockIdx.y;
    if (mtb * 128 >= cnt) return;
    const int i0    = blockIdx.x * 64;
    const int slot0 = g_off[e] + mtb * 128;
    int valid = cnt - mtb * 128; if (valid > 128) valid = 128;

    const int tid = threadIdx.x, lane = tid & 31, wid = tid >> 5;
    const int wm = wid & 1, wn = wid >> 1;       // wm: M half (64), wn: 16-col group (0..3)
    const int g = lane >> 2, tg = lane & 3;
    const uint32_t sb = smem_u32(smem);

    // ---- cp.async fill descriptors ----
    int arow = tid >> 1, aseg = tid & 1;
    int atok = g_tok[slot0 + (arow < valid ? arow : 0)];
    const float4* aSrc = (const float4*)(g_xs + (size_t)atok * H_ + aseg * 16);
    uint32_t aoff[4];
    #pragma unroll
    for (int q = 0; q < 4; q++)
        aoff[q] = (uint32_t)(arow * 128) + (((uint32_t)(aseg * 64 + q * 16)) ^ ((uint32_t)(arow & 7) << 4));

    int bk = tid >> 4, bn4 = tid & 15;
    const float4* gS = (const float4*)(wg + (size_t)e * H_ * I_ + (size_t)bk * I_ + i0) + bn4;
    const float4* uS = (const float4*)(wu + (size_t)e * H_ * I_ + (size_t)bk * I_ + i0) + bn4;
    uint32_t boff[2];
    #pragma unroll
    for (int p = 0; p < 2; p++) { int k = p * 16 + bk; boff[p] = SWZ(k * 256 + bn4 * 16); }

    // ---- fragment addressing ----
    const uint32_t aLdBase = (uint32_t)((wm * 64 + (lane & 15)) * 128);
    const uint32_t aL16 = (uint32_t)((lane >> 4) * 16);
    const uint32_t aXor = (uint32_t)((lane & 7) << 4);
    // B frag col offsets (k-major 256B rows): col n = wn*16 + j*8 + g
    uint32_t colx[2];
    #pragma unroll
    for (int j = 0; j < 2; j++)
        colx[j] = ((uint32_t)(wn * 64 + j * 32 + g * 4)) ^ ((uint32_t)(tg << 5)) ^ ((uint32_t)((wn >> 1) << 4));

    float acc[4][2][2][4];   // [m16][mat G/U][j][q]
    #pragma unroll
    for (int m = 0; m < 4; m++)
        #pragma unroll
        for (int mt2 = 0; mt2 < 2; mt2++)
            #pragma unroll
            for (int j = 0; j < 2; j++)
                #pragma unroll
                for (int q = 0; q < 4; q++) acc[m][mt2][j][q] = 0.f;

    auto ISSUE = [&](int c) {
        int s = c % 3;
        uint32_t A = sb + s * 32768;
        #pragma unroll
        for (int q = 0; q < 4; q++) CPA16(A + aoff[q], aSrc + c * 8 + q);
        uint32_t G = sb + s * 32768 + 16384;
        uint32_t U = sb + s * 32768 + 24576;
        #pragma unroll
        for (int p = 0; p < 2; p++) {
            size_t o = (size_t)(c * 32 + p * 16) * (I_ / 4);
            CPA16(G + boff[p], gS + o);
            CPA16(U + boff[p], uS + o);
        }
    };
    auto MMAS = [&](int s) {
        uint32_t As = sb + s * 32768;
        const char* Gs = smem + s * 32768 + 16384;
        const char* Us = smem + s * 32768 + 24576;
        #pragma unroll
        for (int kt = 0; kt < 4; kt++) {
            uint32_t bf[2][2][2];   // [mat][j][r]
            #pragma unroll
            for (int j = 0; j < 2; j++)
                #pragma unroll
                for (int r = 0; r < 2; r++) {
                    uint32_t off = (uint32_t)((kt * 8 + tg + r * 4) * 256) + colx[j];
                    bf[0][j][r] = RND13(*(const uint32_t*)(Gs + off));
                    bf[1][j][r] = RND13(*(const uint32_t*)(Us + off));
                }
            uint32_t ax = ((uint32_t)(kt * 32) + aL16) ^ aXor;
            #pragma unroll
            for (int m = 0; m < 4; m++) {
                uint32_t a[4];
                LDSM4(a[0], a[1], a[2], a[3], As + aLdBase + m * 2048 + ax);
                #pragma unroll
                for (int j = 0; j < 2; j++) {
                    mma8(acc[m][0][j], a, bf[0][j][0], bf[0][j][1]);
                    mma8(acc[m][1][j], a, bf[1][j][0], bf[1][j][1]);
                }
            }
        }
    };

    ISSUE(0); CPCOMMIT();
    ISSUE(1); CPCOMMIT();
    const int NC = H_ / 32;
    for (int c = 0; c < NC; c++) {
        CPWAIT(1);
        __syncthreads();
        if (c + 2 < NC) ISSUE(c + 2);
        CPCOMMIT();                         // unconditional: exact group count at tail
        MMAS(c % 3);
    }

    // epilogue: act = silu(G)*U, pre-rounded for down GEMM (warp-local G/U pairing)
    #pragma unroll
    for (int m = 0; m < 4; m++) {
        int r0 = wm * 64 + m * 16 + g, r1 = r0 + 8;
        #pragma unroll
        for (int j = 0; j < 2; j++) {
            int c0 = i0 + wn * 16 + j * 8 + tg * 2;
            if (r0 < valid) {
                float gg0 = acc[m][0][j][0], gg1 = acc[m][0][j][1];
                float2 o;
                o.x = rndf(acc[m][1][j][0] * (gg0 / (1.f + __expf(-gg0))));
                o.y = rndf(acc[m][1][j][1] * (gg1 / (1.f + __expf(-gg1))));
                *(float2*)(g_act + (size_t)(slot0 + r0) * I_ + c0) = o;
            }
            if (r1 < valid) {
                float gg2 = acc[m][0][j][2], gg3 = acc[m][0][j][3];
                float2 o;
                o.x = rndf(acc[m][1][j][2] * (gg2 / (1.f + __expf(-gg2))));
                o.y = rndf(acc[m][1][j][3] * (gg3 / (1.f + __expf(-gg3))));
                *(float2*)(g_act + (size_t)(slot0 + r1) * I_ + c0) = o;
            }
        }
    }
}

// ---------------- 6: grouped down GEMM, block N=128, warp tile 64x32, cp.async + scatter ----------------
// 8 warps: wm=wid&1 (M 64), wn=wid>>1 (32-col group 0..3). B smem: two 64-col planes (256B rows).
// Stage: A 16KB | B 16KB = 32KB x3 = 96KB, 2 blocks/SM.
__global__ void __launch_bounds__(256, 2) k_down(const float* __restrict__ wd,
                                                 float* __restrict__ out) {
    extern __shared__ char smem[];
    const int e   = blockIdx.z;
    const int cnt = g_cnt[e];
    const int mtb = blockIdx.y;
    if (mtb * 128 >= cnt) return;
    const int h0    = blockIdx.x * 128;
    const int slot0 = g_off[e] + mtb * 128;
    int valid = cnt - mtb * 128; if (valid > 128) valid = 128;

    const int tid = threadIdx.x, lane = tid & 31, wid = tid >> 5;
    const int wm = wid & 1, wn = wid >> 1;       // wn: 32-col group (0..3); plane = wn>>1
    const int g = lane >> 2, tg = lane & 3;
    const uint32_t sb = smem_u32(smem);

    int arow = tid >> 1, aseg = tid & 1;
    const float4* aSrc = (const float4*)(g_act + (size_t)(slot0 + arow) * I_ + aseg * 16);
    uint32_t aoff[4];
    #pragma unroll
    for (int q = 0; q < 4; q++)
        aoff[q] = (uint32_t)(arow * 128) + (((uint32_t)(aseg * 64 + q * 16)) ^ ((uint32_t)(arow & 7) << 4));

    // B fill: row k = tid>>3 (32 rows), 8 threads/row; per plane 2 float4 each
    int bk = tid >> 3, bf4 = tid & 7;
    const float4* bS = (const float4*)(wd + (size_t)e * I_ * H_ + (size_t)bk * H_ + h0);
    uint32_t boff[2][2];   // [plane][p]
    #pragma unroll
    for (int pl = 0; pl < 2; pl++)
        #pragma unroll
        for (int p = 0; p < 2; p++) {
            int f4 = bf4 * 2 + p;
            boff[pl][p] = (uint32_t)(pl * 8192) + SWZ(bk * 256 + f4 * 16);
        }

    const uint32_t aLdBase = (uint32_t)((wm * 64 + (lane & 15)) * 128);
    const uint32_t aL16 = (uint32_t)((lane >> 4) * 16);
    const uint32_t aXor = (uint32_t)((lane & 7) << 4);
    uint32_t colx[4];   // col n_local = (wn&1)*32 + j*8 + g within plane
    #pragma unroll
    for (int j = 0; j < 4; j++)
        colx[j] = ((uint32_t)((wn & 1) * 128 + j * 32 + g * 4)) ^ ((uint32_t)(tg << 5)) ^ ((uint32_t)((wn & 1) << 4));
    const uint32_t planeOff = (uint32_t)((wn >> 1) * 8192);

    float acc[4][4][4];   // [m16][j][q]
    #pragma unroll
    for (int m = 0; m < 4; m++)
        #pragma unroll
        for (int j = 0; j < 4; j++)
            #pragma unroll
            for (int q = 0; q < 4; q++) acc[m][j][q] = 0.f;

    auto ISSUE = [&](int c) {
        int s = c % 3;
        uint32_t A = sb + s * 32768;
        #pragma unroll
        for (int q = 0; q < 4; q++) CPA16(A + aoff[q], aSrc + c * 8 + q);
        uint32_t B = sb + s * 32768 + 16384;
        const float4* src = bS + (size_t)(c * 32) * (H_ / 4);
        #pragma unroll
        for (int pl = 0; pl < 2; pl++)
            #pragma unroll
            for (int p = 0; p < 2; p++)
                CPA16(B + boff[pl][p], src + pl * 16 + bf4 * 2 + p);
        CPCOMMIT();
    };
    auto MMAS = [&](int s) {
        uint32_t As = sb + s * 32768;
        const char* Bs = smem + s * 32768 + 16384 + planeOff;
        #pragma unroll
        for (int kt = 0; kt < 4; kt++) {
            uint32_t bf[4][2];
            #pragma unroll
            for (int j = 0; j < 4; j++)
                #pragma unroll
                for (int r = 0; r < 2; r++) {
                    uint32_t off = (uint32_t)((kt * 8 + tg + r * 4) * 256) + colx[j];
                    bf[j][r] = RND13(*(const uint32_t*)(Bs + off));
                }
            uint32_t ax = ((uint32_t)(kt * 32) + aL16) ^ aXor;
            #pragma unroll
            for (int m = 0; m < 4; m++) {
                uint32_t a[4];
                LDSM4(a[0], a[1], a[2], a[3], As + aLdBase + m * 2048 + ax);
                #pragma unroll
                for (int j = 0; j < 4; j++)
                    mma8(acc[m][j], a, bf[j][0], bf[j][1]);
            }
        }
    };

    ISSUE(0);
    ISSUE(1);
    const int NC = I_ / 32;
    for (int c = 0; c < NC; c++) {
        CPWAIT(1);
        __syncthreads();
        if (c + 2 < NC) ISSUE(c + 2);
        else CPCOMMIT();                    // keep group count exact at tail
        MMAS(c % 3);
    }

    // epilogue: weighted scatter-add
    #pragma unroll
    for (int m = 0; m < 4; m++) {
        int r0 = wm * 64 + m * 16 + g, r1 = r0 + 8;
        int t0v = 0, t1v = 0; float w0 = 0.f, w1 = 0.f;
        if (r0 < valid) { t0v = g_tok[slot0 + r0]; w0 = g_wt[slot0 + r0]; }
        if (r1 < valid) { t1v = g_tok[slot0 + r1]; w1 = g_wt[slot0 + r1]; }
        #pragma unroll
        for (int j = 0; j < 4; j++) {
            int c0 = h0 + wn * 32 + j * 8 + tg * 2;
            if (r0 < valid) {
                atomicAdd(&out[(size_t)t0v * H_ + c0    ], acc[m][j][0] * w0);
                atomicAdd(&out[(size_t)t0v * H_ + c0 + 1], acc[m][j][1] * w0);
            }
            if (r1 < valid) {
                atomicAdd(&out[(size_t)t1v * H_ + c0    ], acc[m][j][2] * w1);
                atomicAdd(&out[(size_t)t1v * H_ + c0 + 1], acc[m][j][3] * w1);
            }
        }
    }
}

// ---------------- launch ----------------
extern "C" void kernel_launch(void* const* d_in, const int* in_sizes, int n_in,
                              void* d_out, int out_size) {
    const float* x  = (const float*)d_in[0];   // [T, H]
    const float* gw = (const float*)d_in[1];   // [E, H]
    const float* wg = (const float*)d_in[2];   // [E, H, I]
    const float* wu = (const float*)d_in[3];   // [E, H, I]
    const float* wd = (const float*)d_in[4];   // [E, I, H]
    float* out = (float*)d_out;                // [T, H]

    cudaFuncSetAttribute(k_gateup, cudaFuncAttributeMaxDynamicSharedMemorySize, 98304);
    cudaFuncSetAttribute(k_down,   cudaFuncAttributeMaxDynamicSharedMemorySize, 98304);

    k_zero  <<<(T_*H_ + 255) / 256, 256>>>(out, x);
    k_router<<<T_ / 4, 256>>>(x, gw);
    k_topk  <<<T_ / 8, 256>>>();
    k_scan  <<<1, 32>>>();
    k_fill  <<<(NSLOT + 255) / 256, 256>>>();
    k_gateup<<<dim3(I_/64, 8, E_), 256, 98304>>>(wg, wu);
    k_down  <<<dim3(H_/128, 8, E_), 256, 98304>>>(wd, out);
}

// round 15
// speedup vs baseline: 1.1732x; 1.1732x over previous
#include <cuda_runtime.h>
#include <cstdint>
#include <math.h>

#define T_ 1024
#define H_ 2048
#define E_ 64
#define KTOP 8
#define I_ 1024
#define NSLOT (T_*KTOP)

// ---------------- scratch (device globals) ----------------
__device__ float g_xs[T_*H_];           // x rounded-to-nearest at tf32 grid
__device__ float g_logits[T_*E_];
__device__ int   g_cnt[E_];
__device__ int   g_off[E_];
__device__ int   g_cur[E_];
__device__ int   g_tok[NSLOT + 256];
__device__ float g_wt[NSLOT + 256];
__device__ int   g_tk_idx[NSLOT];
__device__ float g_tk_wt[NSLOT];
__device__ float g_act[(size_t)(NSLOT + 256) * I_];   // pre-rounded for down GEMM

#define SWZ(o) ((uint32_t)(o) ^ ((((uint32_t)(o)) >> 3) & 0x70))
// round-to-nearest at the 13-bit truncation the tf32 MMA applies: +half-ulp
#define RND13(b) ((b) + 0x1000u)

__device__ __forceinline__ uint32_t smem_u32(const void* p) {
    uint32_t a;
    asm("{ .reg .u64 t; cvta.to.shared.u64 t, %1; cvt.u32.u64 %0, t; }" : "=r"(a) : "l"(p));
    return a;
}
__device__ __forceinline__ float rndf(float x) {
    return __uint_as_float(RND13(__float_as_uint(x)));
}

#define CPA16(dst, src) \
    asm volatile("cp.async.cg.shared.global [%0], [%1], 16;" :: "r"(dst), "l"(src))
#define CPCOMMIT() asm volatile("cp.async.commit_group;" ::: "memory")
#define CPWAIT(n)  asm volatile("cp.async.wait_group %0;" :: "n"(n) : "memory")

#define LDSM4(r0,r1,r2,r3,a) \
    asm volatile("ldmatrix.sync.aligned.m8n8.x4.shared.b16 {%0,%1,%2,%3}, [%4];" \
        : "=r"(r0), "=r"(r1), "=r"(r2), "=r"(r3) : "r"(a))

__device__ __forceinline__ void mma8(float* c, const uint32_t* a, uint32_t b0, uint32_t b1) {
    asm volatile(
        "mma.sync.aligned.m16n8k8.row.col.f32.tf32.tf32.f32 "
        "{%0,%1,%2,%3}, {%4,%5,%6,%7}, {%8,%9}, {%0,%1,%2,%3};\n"
        : "+f"(c[0]), "+f"(c[1]), "+f"(c[2]), "+f"(c[3])
        : "r"(a[0]), "r"(a[1]), "r"(a[2]), "r"(a[3]), "r"(b0), "r"(b1));
}

// ---------------- 0: router logits (fp32 exact) + zero out + pre-round x + zero counters ----
__global__ void __launch_bounds__(256) k_routerzero(const float* __restrict__ x,
                                                    const float* __restrict__ gw,
                                                    float* __restrict__ out) {
    __shared__ float xs[4 * H_];
    int t0 = blockIdx.x * 4;
    for (int i = threadIdx.x; i < 4 * H_; i += 256) {
        float v = x[(size_t)t0 * H_ + i];
        xs[i] = v;
        g_xs[(size_t)t0 * H_ + i] = rndf(v);   // pre-rounded A operand for gateup
        out [(size_t)t0 * H_ + i] = 0.f;
    }
    if (blockIdx.x == 0 && threadIdx.x < E_) {
        g_cnt[threadIdx.x] = 0; g_cur[threadIdx.x] = 0;
    }
    __syncthreads();
    int warp = threadIdx.x >> 5, lane = threadIdx.x & 31;
    for (int ei = 0; ei < 8; ei++) {
        int e = warp * 8 + ei;
        const float* w = gw + (size_t)e * H_;
        float a0 = 0.f, a1 = 0.f, a2 = 0.f, a3 = 0.f;
        for (int h = lane; h < H_; h += 32) {
            float wv = w[h];
            a0 = fmaf(wv, xs[h],        a0);
            a1 = fmaf(wv, xs[H_   + h], a1);
            a2 = fmaf(wv, xs[2*H_ + h], a2);
            a3 = fmaf(wv, xs[3*H_ + h], a3);
        }
        #pragma unroll
        for (int o = 16; o; o >>= 1) {
            a0 += __shfl_xor_sync(0xffffffffu, a0, o);
            a1 += __shfl_xor_sync(0xffffffffu, a1, o);
            a2 += __shfl_xor_sync(0xffffffffu, a2, o);
            a3 += __shfl_xor_sync(0xffffffffu, a3, o);
        }
        if (lane == 0) {
            g_logits[(t0+0)*E_ + e] = a0;
            g_logits[(t0+1)*E_ + e] = a1;
            g_logits[(t0+2)*E_ + e] = a2;
            g_logits[(t0+3)*E_ + e] = a3;
        }
    }
}

// ---------------- 1: softmax + top-8, warp per token (no local-mem spills) ----------------
__global__ void __launch_bounds__(256) k_topk() {
    int wid = threadIdx.x >> 5, lane = threadIdx.x & 31;
    int t = blockIdx.x * 8 + wid;
    if (t >= T_) return;
    const float* lg = g_logits + t * E_;
    float l0 = lg[lane], l1 = lg[lane + 32];
    float mx = fmaxf(l0, l1);
    #pragma unroll
    for (int o = 16; o; o >>= 1) mx = fmaxf(mx, __shfl_xor_sync(0xffffffffu, mx, o));
    float e0 = expf(l0 - mx), e1 = expf(l1 - mx);
    float s = e0 + e1;
    #pragma unroll
    for (int o = 16; o; o >>= 1) s += __shfl_xor_sync(0xffffffffu, s, o);
    float inv = 1.f / s;
    #pragma unroll
    for (int k = 0; k < KTOP; k++) {
        float v; int idx;
        if (e0 >= e1) { v = e0; idx = lane; } else { v = e1; idx = lane + 32; }
        #pragma unroll
        for (int o = 16; o; o >>= 1) {
            float ov = __shfl_xor_sync(0xffffffffu, v, o);
            int   oi = __shfl_xor_sync(0xffffffffu, idx, o);
            if (ov > v || (ov == v && oi < idx)) { v = ov; idx = oi; }
        }
        if (lane == 0) {
            g_tk_idx[t*KTOP + k] = idx;
            g_tk_wt [t*KTOP + k] = v * inv;
            atomicAdd(&g_cnt[idx], 1);
        }
        if (idx == lane) e0 = -1.f;
        else if (idx == lane + 32) e1 = -1.f;
    }
}

// ---------------- 2: scan + slot fill, single block ----------------
__global__ void __launch_bounds__(1024) k_scanfill() {
    if (threadIdx.x == 0) {
        int acc = 0;
        for (int e = 0; e < E_; e++) { g_off[e] = acc; acc += g_cnt[e]; }
    }
    __syncthreads();
    #pragma unroll
    for (int r = 0; r < NSLOT / 1024; r++) {
        int i = threadIdx.x + r * 1024;
        int t = i >> 3;
        int e = g_tk_idx[i];
        int pos = atomicAdd(&g_cur[e], 1);
        int slot = g_off[e] + pos;
        g_tok[slot] = t;
        g_wt [slot] = g_tk_wt[i];
    }
}

// ---------------- 3: grouped gate/up GEMM, cp.async pipeline + tf32 mma (R13 config) -------
// Block: M=128 slots x N=64 i-cols (G and U). K chunk = 32. 8 warps = 4M x 2N.
// 3 stages x (A 16KB | G 8KB | U 8KB) = 96KB dynamic smem, 2 blocks/SM.
__global__ void __launch_bounds__(256, 2) k_gateup(const float* __restrict__ wg,
                                                   const float* __restrict__ wu) {
    extern __shared__ char smem[];
    const int e   = blockIdx.z;
    const int cnt = g_cnt[e];
    const int mtb = blockIdx.y;
    if (mtb * 128 >= cnt) return;
    const int i0    = blockIdx.x * 64;
    const int slot0 = g_off[e] + mtb * 128;
    int valid = cnt - mtb * 128; if (valid > 128) valid = 128;

    const int tid = threadIdx.x, lane = tid & 31, wid = tid >> 5;
    const int wm = wid & 3, wn = wid >> 2;
    const int wrow = wm * 32;
    const int g = lane >> 2, tg = lane & 3;
    const uint32_t sb = smem_u32(smem);

    // ---- fill descriptors (per-thread, fixed) ----
    int arow = tid >> 1, aseg = tid & 1;
    int atok = g_tok[slot0 + (arow < valid ? arow : 0)];
    const float4* aSrc = (const float4*)(g_xs + (size_t)atok * H_ + aseg * 16);
    uint32_t aoff[4];
    #pragma unroll
    for (int q = 0; q < 4; q++)
        aoff[q] = (uint32_t)(arow * 128) + (((uint32_t)(aseg * 64 + q * 16)) ^ ((uint32_t)(arow & 7) << 4));

    int bk = tid >> 4, bn4 = tid & 15;
    const float4* gS = (const float4*)(wg + (size_t)e * H_ * I_ + (size_t)bk * I_ + i0) + bn4;
    const float4* uS = (const float4*)(wu + (size_t)e * H_ * I_ + (size_t)bk * I_ + i0) + bn4;
    uint32_t boff[2];
    #pragma unroll
    for (int p = 0; p < 2; p++) { int k = p * 16 + bk; boff[p] = SWZ(k * 256 + bn4 * 16); }

    // ---- fragment address precompute ----
    const uint32_t aLdBase = (uint32_t)((wrow + (lane & 15)) * 128);
    const uint32_t aL16 = (uint32_t)((lane >> 4) * 16);
    const uint32_t aXor = (uint32_t)((lane & 7) << 4);
    const uint32_t swzB = (uint32_t)(((2 * tg + wn) & 7) << 4);
    uint32_t inrow[4];
    #pragma unroll
    for (int j = 0; j < 4; j++)
        inrow[j] = ((uint32_t)(wn * 128 + j * 32 + g * 4)) ^ swzB;

    float accG[2][4][4], accU[2][4][4];
    #pragma unroll
    for (int m = 0; m < 2; m++)
        #pragma unroll
        for (int j = 0; j < 4; j++)
            #pragma unroll
            for (int q = 0; q < 4; q++) { accG[m][j][q] = 0.f; accU[m][j][q] = 0.f; }

    auto ISSUE = [&](int c) {
        int s = c % 3;
        uint32_t A = sb + s * 32768;
        #pragma unroll
        for (int q = 0; q < 4; q++) CPA16(A + aoff[q], aSrc + c * 8 + q);
        uint32_t G = sb + s * 32768 + 16384;
        uint32_t U = sb + s * 32768 + 24576;
        #pragma unroll
        for (int p = 0; p < 2; p++) {
            size_t o = (size_t)(c * 32 + p * 16) * (I_ / 4);
            CPA16(G + boff[p], gS + o);
            CPA16(U + boff[p], uS + o);
        }
    };
    auto MMAS = [&](int s) {
        uint32_t As = sb + s * 32768;
        const char* Gs = smem + s * 32768 + 16384;
        const char* Us = smem + s * 32768 + 24576;
        #pragma unroll
        for (int kt = 0; kt < 4; kt++) {
            uint32_t a0[4], a1[4];
            uint32_t ao = As + aLdBase + (((uint32_t)(kt * 32) + aL16) ^ aXor);
            LDSM4(a0[0], a0[1], a0[2], a0[3], ao);
            LDSM4(a1[0], a1[1], a1[2], a1[3], ao + 2048);
            uint32_t bg[4][2], bu[4][2];
            #pragma unroll
            for (int j = 0; j < 4; j++)
                #pragma unroll
                for (int r = 0; r < 2; r++) {
                    uint32_t off = (uint32_t)((kt * 8 + tg + r * 4) * 256) + inrow[j];
                    bg[j][r] = RND13(*(const uint32_t*)(Gs + off));
                    bu[j][r] = RND13(*(const uint32_t*)(Us + off));
                }
            #pragma unroll
            for (int j = 0; j < 4; j++) {
                mma8(accG[0][j], a0, bg[j][0], bg[j][1]);
                mma8(accG[1][j], a1, bg[j][0], bg[j][1]);
                mma8(accU[0][j], a0, bu[j][0], bu[j][1]);
                mma8(accU[1][j], a1, bu[j][0], bu[j][1]);
            }
        }
    };

    ISSUE(0); CPCOMMIT();
    ISSUE(1); CPCOMMIT();
    const int NC = H_ / 32;
    for (int c = 0; c < NC; c++) {
        CPWAIT(1);
        __syncthreads();
        if (c + 2 < NC) ISSUE(c + 2);
        CPCOMMIT();                         // unconditional: exact group count at tail
        MMAS(c % 3);
    }

    // epilogue: act = silu(G)*U, written pre-rounded for the down GEMM
    #pragma unroll
    for (int m = 0; m < 2; m++) {
        int r0 = wrow + m * 16 + g, r1 = r0 + 8;
        #pragma unroll
        for (int j = 0; j < 4; j++) {
            int c0 = i0 + wn * 32 + j * 8 + tg * 2;
            if (r0 < valid) {
                float gg0 = accG[m][j][0], gg1 = accG[m][j][1];
                float2 o;
                o.x = rndf(accU[m][j][0] * (gg0 / (1.f + __expf(-gg0))));
                o.y = rndf(accU[m][j][1] * (gg1 / (1.f + __expf(-gg1))));
                *(float2*)(g_act + (size_t)(slot0 + r0) * I_ + c0) = o;
            }
            if (r1 < valid) {
                float gg2 = accG[m][j][2], gg3 = accG[m][j][3];
                float2 o;
                o.x = rndf(accU[m][j][2] * (gg2 / (1.f + __expf(-gg2))));
                o.y = rndf(accU[m][j][3] * (gg3 / (1.f + __expf(-gg3))));
                *(float2*)(g_act + (size_t)(slot0 + r1) * I_ + c0) = o;
            }
        }
    }
}

// ---------------- 4: grouped down GEMM, cp.async pipeline + tf32 mma + scatter (R13) -------
// Block: M=128 slots x N=64 h-cols. 4 stages x (A 16KB | B 8KB) = 96KB, 2 blocks/SM.
__global__ void __launch_bounds__(256, 2) k_down(const float* __restrict__ wd,
                                                 float* __restrict__ out) {
    extern __shared__ char smem[];
    const int e   = blockIdx.z;
    const int cnt = g_cnt[e];
    const int mtb = blockIdx.y;
    if (mtb * 128 >= cnt) return;
    const int h0    = blockIdx.x * 64;
    const int slot0 = g_off[e] + mtb * 128;
    int valid = cnt - mtb * 128; if (valid > 128) valid = 128;

    const int tid = threadIdx.x, lane = tid & 31, wid = tid >> 5;
    const int wm = wid & 3, wn = wid >> 2;
    const int wrow = wm * 32;
    const int g = lane >> 2, tg = lane & 3;
    const uint32_t sb = smem_u32(smem);

    int arow = tid >> 1, aseg = tid & 1;
    const float4* aSrc = (const float4*)(g_act + (size_t)(slot0 + arow) * I_ + aseg * 16);
    uint32_t aoff[4];
    #pragma unroll
    for (int q = 0; q < 4; q++)
        aoff[q] = (uint32_t)(arow * 128) + (((uint32_t)(aseg * 64 + q * 16)) ^ ((uint32_t)(arow & 7) << 4));

    int bk = tid >> 4, bn4 = tid & 15;
    const float4* bS = (const float4*)(wd + (size_t)e * I_ * H_ + (size_t)bk * H_ + h0) + bn4;
    uint32_t boff[2];
    #pragma unroll
    for (int p = 0; p < 2; p++) { int k = p * 16 + bk; boff[p] = SWZ(k * 256 + bn4 * 16); }

    const uint32_t aLdBase = (uint32_t)((wrow + (lane & 15)) * 128);
    const uint32_t aL16 = (uint32_t)((lane >> 4) * 16);
    const uint32_t aXor = (uint32_t)((lane & 7) << 4);
    const uint32_t swzB = (uint32_t)(((2 * tg + wn) & 7) << 4);
    uint32_t inrow[4];
    #pragma unroll
    for (int j = 0; j < 4; j++)
        inrow[j] = ((uint32_t)(wn * 128 + j * 32 + g * 4)) ^ swzB;

    float acc[2][4][4];
    #pragma unroll
    for (int m = 0; m < 2; m++)
        #pragma unroll
        for (int j = 0; j < 4; j++)
            #pragma unroll
            for (int q = 0; q < 4; q++) acc[m][j][q] = 0.f;

    auto ISSUE = [&](int c) {
        int s = c & 3;
        uint32_t A = sb + s * 24576;
        #pragma unroll
        for (int q = 0; q < 4; q++) CPA16(A + aoff[q], aSrc + c * 8 + q);
        uint32_t B = sb + s * 24576 + 16384;
        #pragma unroll
        for (int p = 0; p < 2; p++)
            CPA16(B + boff[p], bS + (size_t)(c * 32 + p * 16) * (H_ / 4));
    };
    auto MMAS = [&](int s) {
        uint32_t As = sb + s * 24576;
        const char* Bs = smem + s * 24576 + 16384;
        #pragma unroll
        for (int kt = 0; kt < 4; kt++) {
            uint32_t a0[4], a1[4];
            uint32_t ao = As + aLdBase + (((uint32_t)(kt * 32) + aL16) ^ aXor);
            LDSM4(a0[0], a0[1], a0[2], a0[3], ao);
            LDSM4(a1[0], a1[1], a1[2], a1[3], ao + 2048);
            uint32_t bb[4][2];
            #pragma unroll
            for (int j = 0; j < 4; j++)
                #pragma unroll
                for (int r = 0; r < 2; r++) {
                    uint32_t off = (uint32_t)((kt * 8 + tg + r * 4) * 256) + inrow[j];
                    bb[j][r] = RND13(*(const uint32_t*)(Bs + off));
                }
            #pragma unroll
            for (int j = 0; j < 4; j++) {
                mma8(acc[0][j], a0, bb[j][0], bb[j][1]);
                mma8(acc[1][j], a1, bb[j][0], bb[j][1]);
            }
        }
    };

    ISSUE(0); CPCOMMIT();
    ISSUE(1); CPCOMMIT();
    ISSUE(2); CPCOMMIT();
    const int NC = I_ / 32;
    for (int c = 0; c < NC; c++) {
        CPWAIT(2);
        __syncthreads();
        if (c + 3 < NC) ISSUE(c + 3);
        CPCOMMIT();                         // unconditional: exact group count at tail
        MMAS(c & 3);
    }

    // epilogue: weighted scatter-add
    #pragma unroll
    for (int m = 0; m < 2; m++) {
        int r0 = wrow + m * 16 + g, r1 = r0 + 8;
        int t0v = 0, t1v = 0; float w0 = 0.f, w1 = 0.f;
        if (r0 < valid) { t0v = g_tok[slot0 + r0]; w0 = g_wt[slot0 + r0]; }
        if (r1 < valid) { t1v = g_tok[slot0 + r1]; w1 = g_wt[slot0 + r1]; }
        #pragma unroll
        for (int j = 0; j < 4; j++) {
            int c0 = h0 + wn * 32 + j * 8 + tg * 2;
            if (r0 < valid) {
                atomicAdd(&out[(size_t)t0v * H_ + c0    ], acc[m][j][0] * w0);
                atomicAdd(&out[(size_t)t0v * H_ + c0 + 1], acc[m][j][1] * w0);
            }
            if (r1 < valid) {
                atomicAdd(&out[(size_t)t1v * H_ + c0    ], acc[m][j][2] * w1);
                atomicAdd(&out[(size_t)t1v * H_ + c0 + 1], acc[m][j][3] * w1);
            }
        }
    }
}

// ---------------- launch ----------------
extern "C" void kernel_launch(void* const* d_in, const int* in_sizes, int n_in,
                              void* d_out, int out_size) {
    const float* x  = (const float*)d_in[0];   // [T, H]
    const float* gw = (const float*)d_in[1];   // [E, H]
    const float* wg = (const float*)d_in[2];   // [E, H, I]
    const float* wu = (const float*)d_in[3];   // [E, H, I]
    const float* wd = (const float*)d_in[4];   // [E, I, H]
    float* out = (float*)d_out;                // [T, H]

    cudaFuncSetAttribute(k_gateup, cudaFuncAttributeMaxDynamicSharedMemorySize, 98304);
    cudaFuncSetAttribute(k_down,   cudaFuncAttributeMaxDynamicSharedMemorySize, 98304);

    k_routerzero<<<T_ / 4, 256>>>(x, gw, out);
    k_topk      <<<T_ / 8, 256>>>();
    k_scanfill  <<<1, 1024>>>();
    k_gateup    <<<dim3(I_/64, 8, E_), 256, 98304>>>(wg, wu);
    k_down      <<<dim3(H_/64, 8, E_), 256, 98304>>>(wd, out);
}

// round 16
// speedup vs baseline: 1.1777x; 1.0038x over previous
#include <cuda_runtime.h>
#include <cstdint>
#include <math.h>

#define T_ 1024
#define H_ 2048
#define E_ 64
#define KTOP 8
#define I_ 1024
#define NSLOT (T_*KTOP)

// ---------------- scratch (device globals) ----------------
__device__ float g_xs[T_*H_];           // x rounded-to-nearest at tf32 grid
__device__ float g_logits[T_*E_];
__device__ int   g_cnt[E_];
__device__ int   g_off[E_];
__device__ int   g_cur[E_];
__device__ int   g_tok[NSLOT + 256];
__device__ float g_wt[NSLOT + 256];
__device__ int   g_tk_idx[NSLOT];
__device__ float g_tk_wt[NSLOT];
__device__ float g_act[(size_t)(NSLOT + 256) * I_];   // pre-rounded for down GEMM

#define SWZ(o) ((uint32_t)(o) ^ ((((uint32_t)(o)) >> 3) & 0x70))
// round-to-nearest at the 13-bit truncation the tf32 MMA applies: +half-ulp
#define RND13(b) ((b) + 0x1000u)

__device__ __forceinline__ uint32_t smem_u32(const void* p) {
    uint32_t a;
    asm("{ .reg .u64 t; cvta.to.shared.u64 t, %1; cvt.u32.u64 %0, t; }" : "=r"(a) : "l"(p));
    return a;
}
__device__ __forceinline__ float rndf(float x) {
    return __uint_as_float(RND13(__float_as_uint(x)));
}

#define CPA16(dst, src) \
    asm volatile("cp.async.cg.shared.global [%0], [%1], 16;" :: "r"(dst), "l"(src))
#define CPCOMMIT() asm volatile("cp.async.commit_group;" ::: "memory")
#define CPWAIT(n)  asm volatile("cp.async.wait_group %0;" :: "n"(n) : "memory")

#define LDSM4(r0,r1,r2,r3,a) \
    asm volatile("ldmatrix.sync.aligned.m8n8.x4.shared.b16 {%0,%1,%2,%3}, [%4];" \
        : "=r"(r0), "=r"(r1), "=r"(r2), "=r"(r3) : "r"(a))

__device__ __forceinline__ void mma8(float* c, const uint32_t* a, uint32_t b0, uint32_t b1) {
    asm volatile(
        "mma.sync.aligned.m16n8k8.row.col.f32.tf32.tf32.f32 "
        "{%0,%1,%2,%3}, {%4,%5,%6,%7}, {%8,%9}, {%0,%1,%2,%3};\n"
        : "+f"(c[0]), "+f"(c[1]), "+f"(c[2]), "+f"(c[3])
        : "r"(a[0]), "r"(a[1]), "r"(a[2]), "r"(a[3]), "r"(b0), "r"(b1));
}

// ---------------- 0: router logits (fp32 exact) + zero out + pre-round x + zero counters ----
__global__ void __launch_bounds__(256) k_routerzero(const float* __restrict__ x,
                                                    const float* __restrict__ gw,
                                                    float* __restrict__ out) {
    __shared__ float xs[4 * H_];
    int t0 = blockIdx.x * 4;
    for (int i = threadIdx.x; i < 4 * H_; i += 256) {
        float v = x[(size_t)t0 * H_ + i];
        xs[i] = v;
        g_xs[(size_t)t0 * H_ + i] = rndf(v);   // pre-rounded A operand for gateup
        out [(size_t)t0 * H_ + i] = 0.f;
    }
    if (blockIdx.x == 0 && threadIdx.x < E_) {
        g_cnt[threadIdx.x] = 0; g_cur[threadIdx.x] = 0;
    }
    __syncthreads();
    int warp = threadIdx.x >> 5, lane = threadIdx.x & 31;
    for (int ei = 0; ei < 8; ei++) {
        int e = warp * 8 + ei;
        const float* w = gw + (size_t)e * H_;
        float a0 = 0.f, a1 = 0.f, a2 = 0.f, a3 = 0.f;
        for (int h = lane; h < H_; h += 32) {
            float wv = w[h];
            a0 = fmaf(wv, xs[h],        a0);
            a1 = fmaf(wv, xs[H_   + h], a1);
            a2 = fmaf(wv, xs[2*H_ + h], a2);
            a3 = fmaf(wv, xs[3*H_ + h], a3);
        }
        #pragma unroll
        for (int o = 16; o; o >>= 1) {
            a0 += __shfl_xor_sync(0xffffffffu, a0, o);
            a1 += __shfl_xor_sync(0xffffffffu, a1, o);
            a2 += __shfl_xor_sync(0xffffffffu, a2, o);
            a3 += __shfl_xor_sync(0xffffffffu, a3, o);
        }
        if (lane == 0) {
            g_logits[(t0+0)*E_ + e] = a0;
            g_logits[(t0+1)*E_ + e] = a1;
            g_logits[(t0+2)*E_ + e] = a2;
            g_logits[(t0+3)*E_ + e] = a3;
        }
    }
}

// ---------------- 1: softmax + top-8, warp per token (no local-mem spills) ----------------
__global__ void __launch_bounds__(256) k_topk() {
    int wid = threadIdx.x >> 5, lane = threadIdx.x & 31;
    int t = blockIdx.x * 8 + wid;
    if (t >= T_) return;
    const float* lg = g_logits + t * E_;
    float l0 = lg[lane], l1 = lg[lane + 32];
    float mx = fmaxf(l0, l1);
    #pragma unroll
    for (int o = 16; o; o >>= 1) mx = fmaxf(mx, __shfl_xor_sync(0xffffffffu, mx, o));
    float e0 = expf(l0 - mx), e1 = expf(l1 - mx);
    float s = e0 + e1;
    #pragma unroll
    for (int o = 16; o; o >>= 1) s += __shfl_xor_sync(0xffffffffu, s, o);
    float inv = 1.f / s;
    #pragma unroll
    for (int k = 0; k < KTOP; k++) {
        float v; int idx;
        if (e0 >= e1) { v = e0; idx = lane; } else { v = e1; idx = lane + 32; }
        #pragma unroll
        for (int o = 16; o; o >>= 1) {
            float ov = __shfl_xor_sync(0xffffffffu, v, o);
            int   oi = __shfl_xor_sync(0xffffffffu, idx, o);
            if (ov > v || (ov == v && oi < idx)) { v = ov; idx = oi; }
        }
        if (lane == 0) {
            g_tk_idx[t*KTOP + k] = idx;
            g_tk_wt [t*KTOP + k] = v * inv;
            atomicAdd(&g_cnt[idx], 1);
        }
        if (idx == lane) e0 = -1.f;
        else if (idx == lane + 32) e1 = -1.f;
    }
}

// ---------------- 2: scan + slot fill, single block ----------------
__global__ void __launch_bounds__(1024) k_scanfill() {
    if (threadIdx.x == 0) {
        int acc = 0;
        for (int e = 0; e < E_; e++) { g_off[e] = acc; acc += g_cnt[e]; }
    }
    __syncthreads();
    #pragma unroll
    for (int r = 0; r < NSLOT / 1024; r++) {
        int i = threadIdx.x + r * 1024;
        int t = i >> 3;
        int e = g_tk_idx[i];
        int pos = atomicAdd(&g_cur[e], 1);
        int slot = g_off[e] + pos;
        g_tok[slot] = t;
        g_wt [slot] = g_tk_wt[i];
    }
}

// ---------------- 3: grouped gate/up GEMM, cp.async pipeline + tf32 mma (R13 config) -------
// Block: M=128 slots x N=64 i-cols (G and U). K chunk = 32. 8 warps = 4M x 2N.
// 3 stages x (A 16KB | G 8KB | U 8KB) = 96KB dynamic smem, 2 blocks/SM.
__global__ void __launch_bounds__(256, 2) k_gateup(const float* __restrict__ wg,
                                                   const float* __restrict__ wu) {
    extern __shared__ char smem[];
    const int e   = blockIdx.z;
    const int cnt = g_cnt[e];
    const int mtb = blockIdx.y;
    if (mtb * 128 >= cnt) return;
    const int i0    = blockIdx.x * 64;
    const int slot0 = g_off[e] + mtb * 128;
    int valid = cnt - mtb * 128; if (valid > 128) valid = 128;

    const int tid = threadIdx.x, lane = tid & 31, wid = tid >> 5;
    const int wm = wid & 3, wn = wid >> 2;
    const int wrow = wm * 32;
    const int g = lane >> 2, tg = lane & 3;
    const uint32_t sb = smem_u32(smem);

    // ---- fill descriptors (per-thread, fixed) ----
    int arow = tid >> 1, aseg = tid & 1;
    int atok = g_tok[slot0 + (arow < valid ? arow : 0)];
    const float4* aSrc = (const float4*)(g_xs + (size_t)atok * H_ + aseg * 16);
    uint32_t aoff[4];
    #pragma unroll
    for (int q = 0; q < 4; q++)
        aoff[q] = (uint32_t)(arow * 128) + (((uint32_t)(aseg * 64 + q * 16)) ^ ((uint32_t)(arow & 7) << 4));

    int bk = tid >> 4, bn4 = tid & 15;
    const float4* gS = (const float4*)(wg + (size_t)e * H_ * I_ + (size_t)bk * I_ + i0) + bn4;
    const float4* uS = (const float4*)(wu + (size_t)e * H_ * I_ + (size_t)bk * I_ + i0) + bn4;
    uint32_t boff[2];
    #pragma unroll
    for (int p = 0; p < 2; p++) { int k = p * 16 + bk; boff[p] = SWZ(k * 256 + bn4 * 16); }

    // ---- fragment address precompute ----
    const uint32_t aLdBase = (uint32_t)((wrow + (lane & 15)) * 128);
    const uint32_t aL16 = (uint32_t)((lane >> 4) * 16);
    const uint32_t aXor = (uint32_t)((lane & 7) << 4);
    const uint32_t swzB = (uint32_t)(((2 * tg + wn) & 7) << 4);
    uint32_t inrow[4];
    #pragma unroll
    for (int j = 0; j < 4; j++)
        inrow[j] = ((uint32_t)(wn * 128 + j * 32 + g * 4)) ^ swzB;

    float accG[2][4][4], accU[2][4][4];
    #pragma unroll
    for (int m = 0; m < 2; m++)
        #pragma unroll
        for (int j = 0; j < 4; j++)
            #pragma unroll
            for (int q = 0; q < 4; q++) { accG[m][j][q] = 0.f; accU[m][j][q] = 0.f; }

    auto ISSUE = [&](int c) {
        int s = c % 3;
        uint32_t A = sb + s * 32768;
        #pragma unroll
        for (int q = 0; q < 4; q++) CPA16(A + aoff[q], aSrc + c * 8 + q);
        uint32_t G = sb + s * 32768 + 16384;
        uint32_t U = sb + s * 32768 + 24576;
        #pragma unroll
        for (int p = 0; p < 2; p++) {
            size_t o = (size_t)(c * 32 + p * 16) * (I_ / 4);
            CPA16(G + boff[p], gS + o);
            CPA16(U + boff[p], uS + o);
        }
    };
    auto MMAS = [&](int s) {
        uint32_t As = sb + s * 32768;
        const char* Gs = smem + s * 32768 + 16384;
        const char* Us = smem + s * 32768 + 24576;
        #pragma unroll
        for (int kt = 0; kt < 4; kt++) {
            uint32_t a0[4], a1[4];
            uint32_t ao = As + aLdBase + (((uint32_t)(kt * 32) + aL16) ^ aXor);
            LDSM4(a0[0], a0[1], a0[2], a0[3], ao);
            LDSM4(a1[0], a1[1], a1[2], a1[3], ao + 2048);
            uint32_t bg[4][2], bu[4][2];
            #pragma unroll
            for (int j = 0; j < 4; j++)
                #pragma unroll
                for (int r = 0; r < 2; r++) {
                    uint32_t off = (uint32_t)((kt * 8 + tg + r * 4) * 256) + inrow[j];
                    bg[j][r] = RND13(*(const uint32_t*)(Gs + off));
                    bu[j][r] = RND13(*(const uint32_t*)(Us + off));
                }
            #pragma unroll
            for (int j = 0; j < 4; j++) {
                mma8(accG[0][j], a0, bg[j][0], bg[j][1]);
                mma8(accG[1][j], a1, bg[j][0], bg[j][1]);
                mma8(accU[0][j], a0, bu[j][0], bu[j][1]);
                mma8(accU[1][j], a1, bu[j][0], bu[j][1]);
            }
        }
    };

    ISSUE(0); CPCOMMIT();
    ISSUE(1); CPCOMMIT();
    const int NC = H_ / 32;
    for (int c = 0; c < NC; c++) {
        CPWAIT(1);
        __syncthreads();
        if (c + 2 < NC) ISSUE(c + 2);
        CPCOMMIT();                         // unconditional: exact group count at tail
        MMAS(c % 3);
    }

    // epilogue: act = silu(G)*U, written pre-rounded for the down GEMM
    #pragma unroll
    for (int m = 0; m < 2; m++) {
        int r0 = wrow + m * 16 + g, r1 = r0 + 8;
        #pragma unroll
        for (int j = 0; j < 4; j++) {
            int c0 = i0 + wn * 32 + j * 8 + tg * 2;
            if (r0 < valid) {
                float gg0 = accG[m][j][0], gg1 = accG[m][j][1];
                float2 o;
                o.x = rndf(accU[m][j][0] * (gg0 / (1.f + __expf(-gg0))));
                o.y = rndf(accU[m][j][1] * (gg1 / (1.f + __expf(-gg1))));
                *(float2*)(g_act + (size_t)(slot0 + r0) * I_ + c0) = o;
            }
            if (r1 < valid) {
                float gg2 = accG[m][j][2], gg3 = accG[m][j][3];
                float2 o;
                o.x = rndf(accU[m][j][2] * (gg2 / (1.f + __expf(-gg2))));
                o.y = rndf(accU[m][j][3] * (gg3 / (1.f + __expf(-gg3))));
                *(float2*)(g_act + (size_t)(slot0 + r1) * I_ + c0) = o;
            }
        }
    }
}

// ---------------- 4: grouped down GEMM, cp.async pipeline + tf32 mma + scatter (R13) -------
// Block: M=128 slots x N=64 h-cols. 4 stages x (A 16KB | B 8KB) = 96KB, 2 blocks/SM.
__global__ void __launch_bounds__(256, 2) k_down(const float* __restrict__ wd,
                                                 float* __restrict__ out) {
    extern __shared__ char smem[];
    const int e   = blockIdx.z;
    const int cnt = g_cnt[e];
    const int mtb = blockIdx.y;
    if (mtb * 128 >= cnt) return;
    const int h0    = blockIdx.x * 64;
    const int slot0 = g_off[e] + mtb * 128;
    int valid = cnt - mtb * 128; if (valid > 128) valid = 128;

    const int tid = threadIdx.x, lane = tid & 31, wid = tid >> 5;
    const int wm = wid & 3, wn = wid >> 2;
    const int wrow = wm * 32;
    const int g = lane >> 2, tg = lane & 3;
    const uint32_t sb = smem_u32(smem);

    int arow = tid >> 1, aseg = tid & 1;
    const float4* aSrc = (const float4*)(g_act + (size_t)(slot0 + arow) * I_ + aseg * 16);
    uint32_t aoff[4];
    #pragma unroll
    for (int q = 0; q < 4; q++)
        aoff[q] = (uint32_t)(arow * 128) + (((uint32_t)(aseg * 64 + q * 16)) ^ ((uint32_t)(arow & 7) << 4));

    int bk = tid >> 4, bn4 = tid & 15;
    const float4* bS = (const float4*)(wd + (size_t)e * I_ * H_ + (size_t)bk * H_ + h0) + bn4;
    uint32_t boff[2];
    #pragma unroll
    for (int p = 0; p < 2; p++) { int k = p * 16 + bk; boff[p] = SWZ(k * 256 + bn4 * 16); }

    const uint32_t aLdBase = (uint32_t)((wrow + (lane & 15)) * 128);
    const uint32_t aL16 = (uint32_t)((lane >> 4) * 16);
    const uint32_t aXor = (uint32_t)((lane & 7) << 4);
    const uint32_t swzB = (uint32_t)(((2 * tg + wn) & 7) << 4);
    uint32_t inrow[4];
    #pragma unroll
    for (int j = 0; j < 4; j++)
        inrow[j] = ((uint32_t)(wn * 128 + j * 32 + g * 4)) ^ swzB;

    float acc[2][4][4];
    #pragma unroll
    for (int m = 0; m < 2; m++)
        #pragma unroll
        for (int j = 0; j < 4; j++)
            #pragma unroll
            for (int q = 0; q < 4; q++) acc[m][j][q] = 0.f;

    auto ISSUE = [&](int c) {
        int s = c & 3;
        uint32_t A = sb + s * 24576;
        #pragma unroll
        for (int q = 0; q < 4; q++) CPA16(A + aoff[q], aSrc + c * 8 + q);
        uint32_t B = sb + s * 24576 + 16384;
        #pragma unroll
        for (int p = 0; p < 2; p++)
            CPA16(B + boff[p], bS + (size_t)(c * 32 + p * 16) * (H_ / 4));
    };
    auto MMAS = [&](int s) {
        uint32_t As = sb + s * 24576;
        const char* Bs = smem + s * 24576 + 16384;
        #pragma unroll
        for (int kt = 0; kt < 4; kt++) {
            uint32_t a0[4], a1[4];
            uint32_t ao = As + aLdBase + (((uint32_t)(kt * 32) + aL16) ^ aXor);
            LDSM4(a0[0], a0[1], a0[2], a0[3], ao);
            LDSM4(a1[0], a1[1], a1[2], a1[3], ao + 2048);
            uint32_t bb[4][2];
            #pragma unroll
            for (int j = 0; j < 4; j++)
                #pragma unroll
                for (int r = 0; r < 2; r++) {
                    uint32_t off = (uint32_t)((kt * 8 + tg + r * 4) * 256) + inrow[j];
                    bb[j][r] = RND13(*(const uint32_t*)(Bs + off));
                }
            #pragma unroll
            for (int j = 0; j < 4; j++) {
                mma8(acc[0][j], a0, bb[j][0], bb[j][1]);
                mma8(acc[1][j], a1, bb[j][0], bb[j][1]);
            }
        }
    };

    ISSUE(0); CPCOMMIT();
    ISSUE(1); CPCOMMIT();
    ISSUE(2); CPCOMMIT();
    const int NC = I_ / 32;
    for (int c = 0; c < NC; c++) {
        CPWAIT(2);
        __syncthreads();
        if (c + 3 < NC) ISSUE(c + 3);
        CPCOMMIT();                         // unconditional: exact group count at tail
        MMAS(c & 3);
    }

    // epilogue: weighted scatter-add
    #pragma unroll
    for (int m = 0; m < 2; m++) {
        int r0 = wrow + m * 16 + g, r1 = r0 + 8;
        int t0v = 0, t1v = 0; float w0 = 0.f, w1 = 0.f;
        if (r0 < valid) { t0v = g_tok[slot0 + r0]; w0 = g_wt[slot0 + r0]; }
        if (r1 < valid) { t1v = g_tok[slot0 + r1]; w1 = g_wt[slot0 + r1]; }
        #pragma unroll
        for (int j = 0; j < 4; j++) {
            int c0 = h0 + wn * 32 + j * 8 + tg * 2;
            if (r0 < valid) {
                atomicAdd(&out[(size_t)t0v * H_ + c0    ], acc[m][j][0] * w0);
                atomicAdd(&out[(size_t)t0v * H_ + c0 + 1], acc[m][j][1] * w0);
            }
            if (r1 < valid) {
                atomicAdd(&out[(size_t)t1v * H_ + c0    ], acc[m][j][2] * w1);
                atomicAdd(&out[(size_t)t1v * H_ + c0 + 1], acc[m][j][3] * w1);
            }
        }
    }
}

// ---------------- launch ----------------
extern "C" void kernel_launch(void* const* d_in, const int* in_sizes, int n_in,
                              void* d_out, int out_size) {
    const float* x  = (const float*)d_in[0];   // [T, H]
    const float* gw = (const float*)d_in[1];   // [E, H]
    const float* wg = (const float*)d_in[2];   // [E, H, I]
    const float* wu = (const float*)d_in[3];   // [E, H, I]
    const float* wd = (const float*)d_in[4];   // [E, I, H]
    float* out = (float*)d_out;                // [T, H]

    cudaFuncSetAttribute(k_gateup, cudaFuncAttributeMaxDynamicSharedMemorySize, 98304);
    cudaFuncSetAttribute(k_down,   cudaFuncAttributeMaxDynamicSharedMemorySize, 98304);

    k_routerzero<<<T_ / 4, 256>>>(x, gw, out);
    k_topk      <<<T_ / 8, 256>>>();
    k_scanfill  <<<1, 1024>>>();
    k_gateup    <<<dim3(I_/64, 8, E_), 256, 98304>>>(wg, wu);
    k_down      <<<dim3(H_/64, 8, E_), 256, 98304>>>(wd, out);
}